// round 1
// baseline (speedup 1.0000x reference)
#include <cuda_runtime.h>
#include <cstdint>

// ----------------------------------------------------------------------------
// Problem constants (fixed shapes)
// ----------------------------------------------------------------------------
constexpr int BB   = 8;
constexpr int LL   = 1024;
constexpr int DM   = 768;        // d_model
constexpr int DI   = 1536;       // d_inner
constexpr int NS   = 64;         // d_state
constexpr int DTR  = 48;         // dt_rank
constexpr int MTOT = BB * LL;    // 8192 rows
constexpr int XZC  = 2 * DI;     // 3072
constexpr int PROJC = DTR + 2 * NS;  // 176

// ----------------------------------------------------------------------------
// Scratch (device globals; no allocation allowed)
// ----------------------------------------------------------------------------
__device__ float g_xz  [MTOT * XZC];     // (m, 3072)      in-proj output [xs | z]
__device__ float g_xzT [MTOT * XZC];     // (3072, m)      transposed
__device__ float g_uT  [MTOT * DI];      // (d, m)         conv+silu output
__device__ float g_proj[MTOT * PROJC];   // (m, 176)       [dt_r | B | C]
__device__ float g_dtT [MTOT * DI];      // (d, m)         softplus dt
__device__ float g_yT  [MTOT * DI];      // (d, m)         scan output (gated)
__device__ float g_mid [MTOT * DM];      // (m, 768)       inter-layer activation

// ----------------------------------------------------------------------------
// Helpers
// ----------------------------------------------------------------------------
__device__ __forceinline__ float siluf(float x) {
    return x * (1.0f / (1.0f + __expf(-x)));
}
__device__ __forceinline__ float softplusf(float x) {
    return fmaxf(x, 0.0f) + log1pf(__expf(-fabsf(x)));
}

// ----------------------------------------------------------------------------
// GEMM: C[m,n] = sum_k A[m,k] * W[n,k]   (W row-major N x K)
//   ATRANS:  A stored K x MTOT row-major (d-major activations)
//   CTRANS:  C stored N x MTOT row-major
//   SOFTPLUS: C = softplus(acc + bias[n])
// Tiles: 128x64x16, 256 threads, 8x4 per thread. M==MTOT, K%16==0 assumed.
// ----------------------------------------------------------------------------
constexpr int GBM = 128, GBN = 64, GBK = 16, GTM = 8, GTN = 4;

template<bool ATRANS, bool CTRANS, bool SOFTPLUS>
__global__ void __launch_bounds__(256, 2) gemm_kernel(
    const float* __restrict__ A, int lda,
    const float* __restrict__ W,
    const float* __restrict__ bias,
    float* __restrict__ C, int ldc,
    int N, int K)
{
    __shared__ float As[GBK][GBM];      // [k][m]
    __shared__ float Bs[GBK][GBN + 4];  // [k][n], padded for aligned float4

    const int tid = threadIdx.x;
    const int bm  = blockIdx.y * GBM;
    const int bn  = blockIdx.x * GBN;
    const int tx  = tid & 15;
    const int ty  = tid >> 4;

    float acc[GTM][GTN];
    #pragma unroll
    for (int i = 0; i < GTM; i++)
        #pragma unroll
        for (int j = 0; j < GTN; j++) acc[i][j] = 0.0f;

    for (int k0 = 0; k0 < K; k0 += GBK) {
        // ---- load A tile into As[k][m] ----
        if (ATRANS) {
            // A is K x MTOT; direct coalesced float4 loads, no transpose needed
            #pragma unroll
            for (int it = 0; it < 2; it++) {
                int s  = tid * 2 + it;          // 512 float4 slots
                int kk = s >> 5;                // 32 float4 per k-row
                int mc = (s & 31) * 4;
                float4 v = *reinterpret_cast<const float4*>(
                    A + (size_t)(k0 + kk) * MTOT + bm + mc);
                *reinterpret_cast<float4*>(&As[kk][mc]) = v;
            }
        } else {
            // A is MTOT x lda; load float4 along k, scatter-transpose into As
            #pragma unroll
            for (int it = 0; it < 2; it++) {
                int s   = tid * 2 + it;         // 512 float4 slots
                int row = s >> 2;               // 4 float4 per row
                int kc  = (s & 3) * 4;
                float4 v = *reinterpret_cast<const float4*>(
                    A + (size_t)(bm + row) * lda + k0 + kc);
                As[kc + 0][row] = v.x;
                As[kc + 1][row] = v.y;
                As[kc + 2][row] = v.z;
                As[kc + 3][row] = v.w;
            }
        }
        // ---- load B tile (W is N x K) into Bs[k][n] ----
        {
            int n  = tid >> 2;                  // 0..63
            int kc = (tid & 3) * 4;
            float4 v = make_float4(0.f, 0.f, 0.f, 0.f);
            if (bn + n < N)
                v = *reinterpret_cast<const float4*>(
                    W + (size_t)(bn + n) * K + k0 + kc);
            Bs[kc + 0][n] = v.x;
            Bs[kc + 1][n] = v.y;
            Bs[kc + 2][n] = v.z;
            Bs[kc + 3][n] = v.w;
        }
        __syncthreads();

        #pragma unroll
        for (int kk = 0; kk < GBK; kk++) {
            float a[GTM], b[GTN];
            float4 a0 = *reinterpret_cast<const float4*>(&As[kk][ty * GTM]);
            float4 a1 = *reinterpret_cast<const float4*>(&As[kk][ty * GTM + 4]);
            a[0] = a0.x; a[1] = a0.y; a[2] = a0.z; a[3] = a0.w;
            a[4] = a1.x; a[5] = a1.y; a[6] = a1.z; a[7] = a1.w;
            float4 bv = *reinterpret_cast<const float4*>(&Bs[kk][tx * GTN]);
            b[0] = bv.x; b[1] = bv.y; b[2] = bv.z; b[3] = bv.w;
            #pragma unroll
            for (int i = 0; i < GTM; i++)
                #pragma unroll
                for (int j = 0; j < GTN; j++)
                    acc[i][j] = fmaf(a[i], b[j], acc[i][j]);
        }
        __syncthreads();
    }

    // ---- epilogue ----
    #pragma unroll
    for (int i = 0; i < GTM; i++) {
        int m = bm + ty * GTM + i;
        #pragma unroll
        for (int j = 0; j < GTN; j++) {
            int n = bn + tx * GTN + j;
            if (n < N) {
                float v = acc[i][j];
                if (SOFTPLUS) v = softplusf(v + bias[n]);
                if (CTRANS) C[(size_t)n * MTOT + m] = v;
                else        C[(size_t)m * ldc + n]  = v;
            }
        }
    }
}

// ----------------------------------------------------------------------------
// 32x32 tiled transpose: in (R x Ccols) -> out (Ccols x R). R,C % 32 == 0.
// ----------------------------------------------------------------------------
__global__ void transpose_kernel(const float* __restrict__ in,
                                 float* __restrict__ out, int R, int Ccols)
{
    __shared__ float tile[32][33];
    int c0 = blockIdx.x * 32, r0 = blockIdx.y * 32;
    int x = threadIdx.x, y = threadIdx.y;
    #pragma unroll
    for (int i = 0; i < 32; i += 8)
        tile[y + i][x] = in[(size_t)(r0 + y + i) * Ccols + c0 + x];
    __syncthreads();
    #pragma unroll
    for (int i = 0; i < 32; i += 8)
        out[(size_t)(c0 + y + i) * R + r0 + x] = tile[x][y + i];
}

// ----------------------------------------------------------------------------
// Causal depthwise conv (k=4) + SiLU, operating on d-major xs (rows 0..DI-1
// of xzT). One thread per (d, m); fully coalesced.
// ----------------------------------------------------------------------------
__global__ void conv_silu_kernel(const float* __restrict__ xzT,
                                 const float* __restrict__ cw,
                                 const float* __restrict__ cb,
                                 float* __restrict__ uT)
{
    int i = blockIdx.x * blockDim.x + threadIdx.x;   // DI*MTOT threads
    int d = i >> 13;             // / 8192
    int m = i & 8191;
    int t = m & 1023;
    const float* src = xzT + (size_t)d * MTOT + m;
    float w0 = cw[d * 4 + 0], w1 = cw[d * 4 + 1];
    float w2 = cw[d * 4 + 2], w3 = cw[d * 4 + 3];
    float acc = cb[d];
    if (t >= 3) acc = fmaf(src[-3], w0, acc);
    if (t >= 2) acc = fmaf(src[-2], w1, acc);
    if (t >= 1) acc = fmaf(src[-1], w2, acc);
    acc = fmaf(src[0], w3, acc);
    uT[(size_t)d * MTOT + m] = siluf(acc);
}

// ----------------------------------------------------------------------------
// Selective scan. One warp handles 2 channels (d0, d0+1) of one batch b.
// Lane l owns states (l, l+32) of each channel. dt/u/z loaded in 32-t chunks
// (coalesced d-major), broadcast via shfl. B/C read per-t from proj
// (L2-resident, 5.8 MB). Fused epilogue: y = (ys + u*D) * silu(z).
// ----------------------------------------------------------------------------
__global__ void __launch_bounds__(128) ssm_scan_kernel(
    const float* __restrict__ proj,    // (m, 176)
    const float* __restrict__ dtT,     // (d, m)
    const float* __restrict__ uT,      // (d, m)
    const float* __restrict__ xzT,     // (3072, m); z at rows 1536+d
    const float* __restrict__ A_log,   // (d, 64)
    const float* __restrict__ Dparam,  // (d)
    float* __restrict__ yT)            // (d, m)
{
    const unsigned FULL = 0xFFFFFFFFu;
    int w    = (blockIdx.x * blockDim.x + threadIdx.x) >> 5;  // 0..6143
    int lane = threadIdx.x & 31;
    int b  = w / (DI / 2);
    int d0 = (w % (DI / 2)) * 2;
    int d1 = d0 + 1;

    float A00 = -__expf(A_log[(size_t)d0 * NS + lane]);
    float A01 = -__expf(A_log[(size_t)d0 * NS + lane + 32]);
    float A10 = -__expf(A_log[(size_t)d1 * NS + lane]);
    float A11 = -__expf(A_log[(size_t)d1 * NS + lane + 32]);
    float D0 = Dparam[d0], D1 = Dparam[d1];

    float h00 = 0.f, h01 = 0.f, h10 = 0.f, h11 = 0.f;

    for (int tc = 0; tc < LL; tc += 32) {
        size_t mb = (size_t)b * LL + tc;
        float dtv0 = dtT[(size_t)d0 * MTOT + mb + lane];
        float dtv1 = dtT[(size_t)d1 * MTOT + mb + lane];
        float uv0  = uT [(size_t)d0 * MTOT + mb + lane];
        float uv1  = uT [(size_t)d1 * MTOT + mb + lane];
        float zv0  = xzT[(size_t)(DI + d0) * MTOT + mb + lane];
        float zv1  = xzT[(size_t)(DI + d1) * MTOT + mb + lane];

        float y0keep = 0.f, y1keep = 0.f;
        #pragma unroll 8
        for (int j = 0; j < 32; j++) {
            const float* pr = proj + (mb + j) * PROJC;
            float Bn0 = pr[48  + lane];
            float Bn1 = pr[80  + lane];
            float Cn0 = pr[112 + lane];
            float Cn1 = pr[144 + lane];
            float dt0 = __shfl_sync(FULL, dtv0, j);
            float dt1 = __shfl_sync(FULL, dtv1, j);
            float u0  = __shfl_sync(FULL, uv0, j);
            float u1  = __shfl_sync(FULL, uv1, j);
            float du0 = dt0 * u0;
            float du1 = dt1 * u1;
            h00 = fmaf(__expf(dt0 * A00), h00, du0 * Bn0);
            h01 = fmaf(__expf(dt0 * A01), h01, du0 * Bn1);
            h10 = fmaf(__expf(dt1 * A10), h10, du1 * Bn0);
            h11 = fmaf(__expf(dt1 * A11), h11, du1 * Bn1);
            float y0 = fmaf(h00, Cn0, h01 * Cn1);
            float y1 = fmaf(h10, Cn0, h11 * Cn1);
            #pragma unroll
            for (int off = 16; off; off >>= 1) {
                y0 += __shfl_xor_sync(FULL, y0, off);
                y1 += __shfl_xor_sync(FULL, y1, off);
            }
            if (lane == j) { y0keep = y0; y1keep = y1; }
        }
        // lane l holds result for t = tc + l
        float out0 = (y0keep + uv0 * D0) * siluf(zv0);
        float out1 = (y1keep + uv1 * D1) * siluf(zv1);
        yT[(size_t)d0 * MTOT + mb + lane] = out0;
        yT[(size_t)d1 * MTOT + mb + lane] = out1;
    }
}

// ----------------------------------------------------------------------------
// kernel_launch: 7 kernels per layer, 2 layers. All on the default stream,
// fully graph-capturable (no sync, no alloc).
// ----------------------------------------------------------------------------
extern "C" void kernel_launch(void* const* d_in, const int* in_sizes, int n_in,
                              void* d_out, int out_size)
{
    const float* x     = (const float*)d_in[0];
    const float* W_in  = (const float*)d_in[1];
    const float* cw    = (const float*)d_in[2];
    const float* cb    = (const float*)d_in[3];
    const float* W_x   = (const float*)d_in[4];
    const float* W_dt  = (const float*)d_in[5];
    const float* b_dt  = (const float*)d_in[6];
    const float* A_log = (const float*)d_in[7];
    const float* Dp    = (const float*)d_in[8];
    const float* W_out = (const float*)d_in[9];

    float *xz, *xzT, *uT, *proj, *dtT, *yT, *mid;
    cudaGetSymbolAddress((void**)&xz,   g_xz);
    cudaGetSymbolAddress((void**)&xzT,  g_xzT);
    cudaGetSymbolAddress((void**)&uT,   g_uT);
    cudaGetSymbolAddress((void**)&proj, g_proj);
    cudaGetSymbolAddress((void**)&dtT,  g_dtT);
    cudaGetSymbolAddress((void**)&yT,   g_yT);
    cudaGetSymbolAddress((void**)&mid,  g_mid);

    const dim3 tb256(256);

    for (int l = 0; l < 2; l++) {
        const float* xin = (l == 0) ? x : mid;
        float* xout = (l == 1) ? (float*)d_out : mid;

        // 1. in-proj: xz[m,3072] = xin @ W_in^T
        gemm_kernel<false, false, false>
            <<<dim3(XZC / GBN, MTOT / GBM), tb256>>>(
                xin, DM, W_in + (size_t)l * XZC * DM, nullptr,
                xz, XZC, XZC, DM);

        // 2. transpose xz -> xzT (d-major xs and z)
        transpose_kernel<<<dim3(XZC / 32, MTOT / 32), dim3(32, 8)>>>(
            xz, xzT, MTOT, XZC);

        // 3. causal depthwise conv + silu -> uT (d-major)
        conv_silu_kernel<<<(DI * MTOT) / 256, tb256>>>(
            xzT, cw + (size_t)l * DI * 4, cb + (size_t)l * DI, uT);

        // 4. x-proj: proj[m,176] = u @ W_x^T   (A transposed input)
        gemm_kernel<true, false, false>
            <<<dim3((PROJC + GBN - 1) / GBN, MTOT / GBM), tb256>>>(
                uT, 0, W_x + (size_t)l * PROJC * DI, nullptr,
                proj, PROJC, PROJC, DI);

        // 5. dt: dtT[d,m] = softplus(proj[:, :48] @ W_dt^T + b_dt)
        gemm_kernel<false, true, true>
            <<<dim3(DI / GBN, MTOT / GBM), tb256>>>(
                proj, PROJC, W_dt + (size_t)l * DI * DTR,
                b_dt + (size_t)l * DI, dtT, 0, DI, DTR);

        // 6. selective scan + skip + gate -> yT (d-major)
        ssm_scan_kernel<<<(BB * (DI / 2)) / 4, dim3(128)>>>(
            proj, dtT, uT, xzT,
            A_log + (size_t)l * DI * NS, Dp + (size_t)l * DI, yT);

        // 7. out-proj: xout[m,768] = y @ W_out^T   (A transposed input)
        gemm_kernel<true, false, false>
            <<<dim3(DM / GBN, MTOT / GBM), tb256>>>(
                yT, 0, W_out + (size_t)l * DM * DI, nullptr,
                xout, DM, DM, DI);
    }
}

// round 4
// speedup vs baseline: 1.0162x; 1.0162x over previous
#include <cuda_runtime.h>
#include <cstdint>

// ----------------------------------------------------------------------------
// Problem constants (fixed shapes)
// ----------------------------------------------------------------------------
constexpr int BB   = 8;
constexpr int LL   = 1024;
constexpr int DM   = 768;        // d_model
constexpr int DI   = 1536;       // d_inner
constexpr int NS   = 64;         // d_state
constexpr int DTR  = 48;         // dt_rank
constexpr int MTOT = BB * LL;    // 8192 rows
constexpr int XZC  = 2 * DI;     // 3072
constexpr int PROJC = DTR + 2 * NS;  // 176

// ----------------------------------------------------------------------------
// Scratch (device globals; no allocation allowed)
// ----------------------------------------------------------------------------
__device__ float g_xz  [MTOT * XZC];     // (m, 3072)      in-proj output [xs | z]
__device__ float g_xzT [MTOT * XZC];     // (3072, m)      transposed
__device__ float g_uT  [MTOT * DI];      // (d, m)         conv+silu output
__device__ float g_proj[MTOT * PROJC];   // (m, 176)       [dt_r | B | C]
__device__ float g_dtT [MTOT * DI];      // (d, m)         softplus dt
__device__ float g_yT  [MTOT * DI];      // (d, m)         scan output (gated)
__device__ float g_mid [MTOT * DM];      // (m, 768)       inter-layer activation

// ----------------------------------------------------------------------------
// Helpers
// ----------------------------------------------------------------------------
__device__ __forceinline__ float siluf(float x) {
    return x * (1.0f / (1.0f + __expf(-x)));
}
__device__ __forceinline__ float softplusf(float x) {
    return fmaxf(x, 0.0f) + log1pf(__expf(-fabsf(x)));
}

// ============================================================================
// Big GEMM: 128x128x16 tiles, double-buffered, 256 threads, 8x8 per thread.
//   C[m,n] = sum_k A[m,k] * W[n,k]   (W row-major N x K)
//   ATRANS:  A stored K x MTOT row-major (d-major activations)
//   CTRANS:  C stored N x MTOT row-major (smem-staged transpose, aliases As)
//   SOFTPLUS: C = softplus(acc + bias[n])
// Requires: N % 128 == 0, K % 16 == 0, M == MTOT.
// ============================================================================
constexpr int BM = 128, BN = 128, BK = 16;
constexpr int SAP = BM + 4;   // padded row (132 words, 16B-aligned stride)

template<bool ATRANS, bool CTRANS, bool SOFTPLUS>
__global__ void __launch_bounds__(256, 2) gemm128_kernel(
    const float* __restrict__ A, int lda,
    const float* __restrict__ W,        // N x K
    const float* __restrict__ bias,
    float* __restrict__ C, int ldc,
    int N, int K)
{
    __shared__ float As[2][BK][SAP];    // 2*16*132 = 4224 words
    __shared__ float Bs[2][BK][SAP];

    const int tid = threadIdx.x;
    const int bm  = blockIdx.y * BM;
    const int bn  = blockIdx.x * BN;
    const int tx  = tid & 15;
    const int ty  = tid >> 4;

    float acc[8][8];
    #pragma unroll
    for (int i = 0; i < 8; i++)
        #pragma unroll
        for (int j = 0; j < 8; j++) acc[i][j] = 0.0f;

    float4 pa[2], pb[2];

    auto gloadA = [&](int k0) {
        #pragma unroll
        for (int it = 0; it < 2; it++) {
            int s = tid + it * 256;                 // 512 float4 slots
            if (ATRANS) {
                int kk = s >> 5;                    // 0..15
                int mc = (s & 31) * 4;              // 0..124
                pa[it] = *reinterpret_cast<const float4*>(
                    A + (size_t)(k0 + kk) * MTOT + bm + mc);
            } else {
                int row = s >> 2;                   // 0..127
                int kc  = (s & 3) * 4;              // 0,4,8,12
                pa[it] = *reinterpret_cast<const float4*>(
                    A + (size_t)(bm + row) * lda + k0 + kc);
            }
        }
    };
    auto gloadB = [&](int k0) {
        #pragma unroll
        for (int it = 0; it < 2; it++) {
            int s = tid + it * 256;
            int n  = s >> 2;
            int kc = (s & 3) * 4;
            pb[it] = *reinterpret_cast<const float4*>(
                W + (size_t)(bn + n) * K + k0 + kc);
        }
    };
    auto sstore = [&](int st) {
        #pragma unroll
        for (int it = 0; it < 2; it++) {
            int s = tid + it * 256;
            if (ATRANS) {
                int kk = s >> 5;
                int mc = (s & 31) * 4;
                *reinterpret_cast<float4*>(&As[st][kk][mc]) = pa[it];
            } else {
                int row = s >> 2;
                int kc  = (s & 3) * 4;
                As[st][kc + 0][row] = pa[it].x;
                As[st][kc + 1][row] = pa[it].y;
                As[st][kc + 2][row] = pa[it].z;
                As[st][kc + 3][row] = pa[it].w;
            }
            int n  = s >> 2;
            int kc = (s & 3) * 4;
            Bs[st][kc + 0][n] = pb[it].x;
            Bs[st][kc + 1][n] = pb[it].y;
            Bs[st][kc + 2][n] = pb[it].z;
            Bs[st][kc + 3][n] = pb[it].w;
        }
    };

    // prologue: fill stage 0
    gloadA(0); gloadB(0);
    sstore(0);
    __syncthreads();

    const int kt = K / BK;
    int st = 0;
    for (int it = 0; it < kt; it++) {
        const bool more = (it + 1) < kt;
        if (more) { gloadA((it + 1) * BK); gloadB((it + 1) * BK); }

        #pragma unroll
        for (int kk = 0; kk < BK; kk++) {
            float a[8], b[8];
            float4 a0 = *reinterpret_cast<const float4*>(&As[st][kk][ty * 4]);
            float4 a1 = *reinterpret_cast<const float4*>(&As[st][kk][64 + ty * 4]);
            float4 b0 = *reinterpret_cast<const float4*>(&Bs[st][kk][tx * 4]);
            float4 b1 = *reinterpret_cast<const float4*>(&Bs[st][kk][64 + tx * 4]);
            a[0]=a0.x; a[1]=a0.y; a[2]=a0.z; a[3]=a0.w;
            a[4]=a1.x; a[5]=a1.y; a[6]=a1.z; a[7]=a1.w;
            b[0]=b0.x; b[1]=b0.y; b[2]=b0.z; b[3]=b0.w;
            b[4]=b1.x; b[5]=b1.y; b[6]=b1.z; b[7]=b1.w;
            #pragma unroll
            for (int i = 0; i < 8; i++)
                #pragma unroll
                for (int j = 0; j < 8; j++)
                    acc[i][j] = fmaf(a[i], b[j], acc[i][j]);
        }
        if (more) {
            sstore(st ^ 1);
            __syncthreads();
        }
        st ^= 1;
    }

    // ---- epilogue ----
    if constexpr (CTRANS) {
        // Transpose staging buffer ALIASES As (dead after mainloop):
        // As is 2*16*132 = 4224 words == 32*132 — exactly Ts[32][SAP].
        float (*Ts)[SAP] = reinterpret_cast<float (*)[SAP]>(&As[0][0][0]);
        #pragma unroll
        for (int p = 0; p < 4; p++) {
            const int grp = p >> 1, txsel = p & 1;
            __syncthreads();   // protect As reuse (p=0) / previous phase (p>0)
            if ((tx >> 3) == txsel) {
                #pragma unroll
                for (int i = 0; i < 8; i++) {
                    int ml = (i < 4) ? ty * 4 + i : 64 + ty * 4 + (i - 4);
                    #pragma unroll
                    for (int j = 0; j < 4; j++) {
                        int jj = grp * 4 + j;
                        int nn = (tx & 7) * 4 + j;
                        float v = acc[i][jj];
                        if (SOFTPLUS) v = softplusf(v + bias[bn + p * 32 + nn]);
                        Ts[nn][ml] = v;
                    }
                }
            }
            __syncthreads();
            int nn = tid >> 3;
            int mm = (tid & 7) * 16;
            size_t base = (size_t)(bn + p * 32 + nn) * MTOT + bm + mm;
            #pragma unroll
            for (int q = 0; q < 4; q++)
                *reinterpret_cast<float4*>(&C[base + q * 4]) =
                    *reinterpret_cast<const float4*>(&Ts[nn][mm + q * 4]);
        }
    } else {
        #pragma unroll
        for (int i = 0; i < 8; i++) {
            int m = bm + ((i < 4) ? ty * 4 + i : 64 + ty * 4 + (i - 4));
            float4 v0 = make_float4(acc[i][0], acc[i][1], acc[i][2], acc[i][3]);
            float4 v1 = make_float4(acc[i][4], acc[i][5], acc[i][6], acc[i][7]);
            *reinterpret_cast<float4*>(&C[(size_t)m * ldc + bn + tx * 4])      = v0;
            *reinterpret_cast<float4*>(&C[(size_t)m * ldc + bn + 64 + tx * 4]) = v1;
        }
    }
}

// ============================================================================
// Small GEMM (x-proj only, N=176): 128x64x16 tiles, 256 threads, 8x4/thread.
// ============================================================================
constexpr int GBM = 128, GBN = 64, GBK = 16, GTM = 8, GTN = 4;

__global__ void __launch_bounds__(256, 2) gemm_small_kernel(
    const float* __restrict__ A,        // K x MTOT (d-major)
    const float* __restrict__ W,
    float* __restrict__ C, int ldc,
    int N, int K)
{
    __shared__ float As[GBK][GBM];
    __shared__ float Bs[GBK][GBN + 4];

    const int tid = threadIdx.x;
    const int bm  = blockIdx.y * GBM;
    const int bn  = blockIdx.x * GBN;
    const int tx  = tid & 15;
    const int ty  = tid >> 4;

    float acc[GTM][GTN];
    #pragma unroll
    for (int i = 0; i < GTM; i++)
        #pragma unroll
        for (int j = 0; j < GTN; j++) acc[i][j] = 0.0f;

    for (int k0 = 0; k0 < K; k0 += GBK) {
        #pragma unroll
        for (int it = 0; it < 2; it++) {
            int s  = tid * 2 + it;
            int kk = s >> 5;
            int mc = (s & 31) * 4;
            float4 v = *reinterpret_cast<const float4*>(
                A + (size_t)(k0 + kk) * MTOT + bm + mc);
            *reinterpret_cast<float4*>(&As[kk][mc]) = v;
        }
        {
            int n  = tid >> 2;
            int kc = (tid & 3) * 4;
            float4 v = make_float4(0.f, 0.f, 0.f, 0.f);
            if (bn + n < N)
                v = *reinterpret_cast<const float4*>(
                    W + (size_t)(bn + n) * K + k0 + kc);
            Bs[kc + 0][n] = v.x;
            Bs[kc + 1][n] = v.y;
            Bs[kc + 2][n] = v.z;
            Bs[kc + 3][n] = v.w;
        }
        __syncthreads();

        #pragma unroll
        for (int kk = 0; kk < GBK; kk++) {
            float a[GTM], b[GTN];
            float4 a0 = *reinterpret_cast<const float4*>(&As[kk][ty * GTM]);
            float4 a1 = *reinterpret_cast<const float4*>(&As[kk][ty * GTM + 4]);
            a[0]=a0.x; a[1]=a0.y; a[2]=a0.z; a[3]=a0.w;
            a[4]=a1.x; a[5]=a1.y; a[6]=a1.z; a[7]=a1.w;
            float4 bv = *reinterpret_cast<const float4*>(&Bs[kk][tx * GTN]);
            b[0]=bv.x; b[1]=bv.y; b[2]=bv.z; b[3]=bv.w;
            #pragma unroll
            for (int i = 0; i < GTM; i++)
                #pragma unroll
                for (int j = 0; j < GTN; j++)
                    acc[i][j] = fmaf(a[i], b[j], acc[i][j]);
        }
        __syncthreads();
    }

    #pragma unroll
    for (int i = 0; i < GTM; i++) {
        int m = bm + ty * GTM + i;
        #pragma unroll
        for (int j = 0; j < GTN; j++) {
            int n = bn + tx * GTN + j;
            if (n < N) C[(size_t)m * ldc + n] = acc[i][j];
        }
    }
}

// ----------------------------------------------------------------------------
// 32x32 tiled transpose: in (R x Ccols) -> out (Ccols x R). R,C % 32 == 0.
// ----------------------------------------------------------------------------
__global__ void transpose_kernel(const float* __restrict__ in,
                                 float* __restrict__ out, int R, int Ccols)
{
    __shared__ float tile[32][33];
    int c0 = blockIdx.x * 32, r0 = blockIdx.y * 32;
    int x = threadIdx.x, y = threadIdx.y;
    #pragma unroll
    for (int i = 0; i < 32; i += 8)
        tile[y + i][x] = in[(size_t)(r0 + y + i) * Ccols + c0 + x];
    __syncthreads();
    #pragma unroll
    for (int i = 0; i < 32; i += 8)
        out[(size_t)(c0 + y + i) * R + r0 + x] = tile[x][y + i];
}

// ----------------------------------------------------------------------------
// Causal depthwise conv (k=4) + SiLU on d-major xs (rows 0..DI-1 of xzT).
// ----------------------------------------------------------------------------
__global__ void conv_silu_kernel(const float* __restrict__ xzT,
                                 const float* __restrict__ cw,
                                 const float* __restrict__ cb,
                                 float* __restrict__ uT)
{
    int i = blockIdx.x * blockDim.x + threadIdx.x;   // DI*MTOT threads
    int d = i >> 13;             // / 8192
    int m = i & 8191;
    int t = m & 1023;
    const float* src = xzT + (size_t)d * MTOT + m;
    float w0 = cw[d * 4 + 0], w1 = cw[d * 4 + 1];
    float w2 = cw[d * 4 + 2], w3 = cw[d * 4 + 3];
    float acc = cb[d];
    if (t >= 3) acc = fmaf(src[-3], w0, acc);
    if (t >= 2) acc = fmaf(src[-2], w1, acc);
    if (t >= 1) acc = fmaf(src[-1], w2, acc);
    acc = fmaf(src[0], w3, acc);
    uT[(size_t)d * MTOT + m] = siluf(acc);
}

// ----------------------------------------------------------------------------
// Selective scan. One warp = 2 channels of one batch; lane l owns states
// (l, l+32). Fused skip + gate epilogue.
// ----------------------------------------------------------------------------
__global__ void __launch_bounds__(128) ssm_scan_kernel(
    const float* __restrict__ proj,    // (m, 176)
    const float* __restrict__ dtT,     // (d, m)
    const float* __restrict__ uT,      // (d, m)
    const float* __restrict__ xzT,     // (3072, m); z at rows 1536+d
    const float* __restrict__ A_log,   // (d, 64)
    const float* __restrict__ Dparam,  // (d)
    float* __restrict__ yT)            // (d, m)
{
    const unsigned FULL = 0xFFFFFFFFu;
    int w    = (blockIdx.x * blockDim.x + threadIdx.x) >> 5;  // 0..6143
    int lane = threadIdx.x & 31;
    int b  = w / (DI / 2);
    int d0 = (w % (DI / 2)) * 2;
    int d1 = d0 + 1;

    float A00 = -__expf(A_log[(size_t)d0 * NS + lane]);
    float A01 = -__expf(A_log[(size_t)d0 * NS + lane + 32]);
    float A10 = -__expf(A_log[(size_t)d1 * NS + lane]);
    float A11 = -__expf(A_log[(size_t)d1 * NS + lane + 32]);
    float D0 = Dparam[d0], D1 = Dparam[d1];

    float h00 = 0.f, h01 = 0.f, h10 = 0.f, h11 = 0.f;

    for (int tc = 0; tc < LL; tc += 32) {
        size_t mb = (size_t)b * LL + tc;
        float dtv0 = dtT[(size_t)d0 * MTOT + mb + lane];
        float dtv1 = dtT[(size_t)d1 * MTOT + mb + lane];
        float uv0  = uT [(size_t)d0 * MTOT + mb + lane];
        float uv1  = uT [(size_t)d1 * MTOT + mb + lane];
        float zv0  = xzT[(size_t)(DI + d0) * MTOT + mb + lane];
        float zv1  = xzT[(size_t)(DI + d1) * MTOT + mb + lane];

        float y0keep = 0.f, y1keep = 0.f;
        #pragma unroll 8
        for (int j = 0; j < 32; j++) {
            const float* pr = proj + (mb + j) * PROJC;
            float Bn0 = pr[48  + lane];
            float Bn1 = pr[80  + lane];
            float Cn0 = pr[112 + lane];
            float Cn1 = pr[144 + lane];
            float dt0 = __shfl_sync(FULL, dtv0, j);
            float dt1 = __shfl_sync(FULL, dtv1, j);
            float u0  = __shfl_sync(FULL, uv0, j);
            float u1  = __shfl_sync(FULL, uv1, j);
            float du0 = dt0 * u0;
            float du1 = dt1 * u1;
            h00 = fmaf(__expf(dt0 * A00), h00, du0 * Bn0);
            h01 = fmaf(__expf(dt0 * A01), h01, du0 * Bn1);
            h10 = fmaf(__expf(dt1 * A10), h10, du1 * Bn0);
            h11 = fmaf(__expf(dt1 * A11), h11, du1 * Bn1);
            float y0 = fmaf(h00, Cn0, h01 * Cn1);
            float y1 = fmaf(h10, Cn0, h11 * Cn1);
            #pragma unroll
            for (int off = 16; off; off >>= 1) {
                y0 += __shfl_xor_sync(FULL, y0, off);
                y1 += __shfl_xor_sync(FULL, y1, off);
            }
            if (lane == j) { y0keep = y0; y1keep = y1; }
        }
        float out0 = (y0keep + uv0 * D0) * siluf(zv0);
        float out1 = (y1keep + uv1 * D1) * siluf(zv1);
        yT[(size_t)d0 * MTOT + mb + lane] = out0;
        yT[(size_t)d1 * MTOT + mb + lane] = out1;
    }
}

// ----------------------------------------------------------------------------
// kernel_launch
// ----------------------------------------------------------------------------
extern "C" void kernel_launch(void* const* d_in, const int* in_sizes, int n_in,
                              void* d_out, int out_size)
{
    const float* x     = (const float*)d_in[0];
    const float* W_in  = (const float*)d_in[1];
    const float* cw    = (const float*)d_in[2];
    const float* cb    = (const float*)d_in[3];
    const float* W_x   = (const float*)d_in[4];
    const float* W_dt  = (const float*)d_in[5];
    const float* b_dt  = (const float*)d_in[6];
    const float* A_log = (const float*)d_in[7];
    const float* Dp    = (const float*)d_in[8];
    const float* W_out = (const float*)d_in[9];

    float *xz, *xzT, *uT, *proj, *dtT, *yT, *mid;
    cudaGetSymbolAddress((void**)&xz,   g_xz);
    cudaGetSymbolAddress((void**)&xzT,  g_xzT);
    cudaGetSymbolAddress((void**)&uT,   g_uT);
    cudaGetSymbolAddress((void**)&proj, g_proj);
    cudaGetSymbolAddress((void**)&dtT,  g_dtT);
    cudaGetSymbolAddress((void**)&yT,   g_yT);
    cudaGetSymbolAddress((void**)&mid,  g_mid);

    const dim3 tb256(256);

    for (int l = 0; l < 2; l++) {
        const float* xin = (l == 0) ? x : mid;
        float* xout = (l == 1) ? (float*)d_out : mid;

        // 1. in-proj: xz[m,3072] = xin @ W_in^T
        gemm128_kernel<false, false, false>
            <<<dim3(XZC / BN, MTOT / BM), tb256>>>(
                xin, DM, W_in + (size_t)l * XZC * DM, nullptr,
                xz, XZC, XZC, DM);

        // 2. transpose xz -> xzT (d-major xs and z)
        transpose_kernel<<<dim3(XZC / 32, MTOT / 32), dim3(32, 8)>>>(
            xz, xzT, MTOT, XZC);

        // 3. causal depthwise conv + silu -> uT (d-major)
        conv_silu_kernel<<<(DI * MTOT) / 256, tb256>>>(
            xzT, cw + (size_t)l * DI * 4, cb + (size_t)l * DI, uT);

        // 4. x-proj: proj[m,176] = u @ W_x^T   (d-major A input)
        gemm_small_kernel
            <<<dim3((PROJC + GBN - 1) / GBN, MTOT / GBM), tb256>>>(
                uT, W_x + (size_t)l * PROJC * DI,
                proj, PROJC, PROJC, DI);

        // 5. dt: dtT[d,m] = softplus(proj[:, :48] @ W_dt^T + b_dt)
        gemm128_kernel<false, true, true>
            <<<dim3(DI / BN, MTOT / BM), tb256>>>(
                proj, PROJC, W_dt + (size_t)l * DI * DTR,
                b_dt + (size_t)l * DI, dtT, 0, DI, DTR);

        // 6. selective scan + skip + gate -> yT (d-major)
        ssm_scan_kernel<<<(BB * (DI / 2)) / 4, dim3(128)>>>(
            proj, dtT, uT, xzT,
            A_log + (size_t)l * DI * NS, Dp + (size_t)l * DI, yT);

        // 7. out-proj: xout[m,768] = y @ W_out^T   (d-major A input)
        gemm128_kernel<true, false, false>
            <<<dim3(DM / BN, MTOT / BM), tb256>>>(
                yT, 0, W_out + (size_t)l * DM * DI, nullptr,
                xout, DM, DM, DI);
    }
}

// round 5
// speedup vs baseline: 1.7048x; 1.6776x over previous
#include <cuda_runtime.h>
#include <cstdint>

// ----------------------------------------------------------------------------
// Problem constants (fixed shapes)
// ----------------------------------------------------------------------------
constexpr int BB   = 8;
constexpr int LL   = 1024;
constexpr int DM   = 768;        // d_model
constexpr int DI   = 1536;       // d_inner
constexpr int NS   = 64;         // d_state
constexpr int DTR  = 48;         // dt_rank
constexpr int MTOT = BB * LL;    // 8192 rows
constexpr int XZC  = 2 * DI;     // 3072
constexpr int PROJC = DTR + 2 * NS;  // 176

// ----------------------------------------------------------------------------
// Scratch (device globals; no allocation allowed)
// ----------------------------------------------------------------------------
__device__ float g_xz  [MTOT * XZC];     // (m, 3072) in-proj out; later dt_m
__device__ float g_xzT [MTOT * XZC];     // (3072, m) transposed
__device__ float g_uT  [MTOT * DI];      // (d, m)    conv+silu output
__device__ float g_proj[MTOT * PROJC];   // (m, 176)  [dt_r | B | C]
__device__ float g_dtT [MTOT * DI];      // (d, m)    softplus dt
__device__ float g_yT  [MTOT * DI];      // (d, m)    scan output (gated)
__device__ float g_mid [MTOT * DM];      // (m, 768)  inter-layer activation

// ----------------------------------------------------------------------------
// Helpers
// ----------------------------------------------------------------------------
__device__ __forceinline__ float siluf(float x) {
    return x * (1.0f / (1.0f + __expf(-x)));
}
__device__ __forceinline__ float softplusf(float x) {
    return fmaxf(x, 0.0f) + log1pf(__expf(-fabsf(x)));
}
__device__ __forceinline__ uint32_t f2tf32(float x) {
    uint32_t r;
    asm("cvt.rna.tf32.f32 %0, %1;" : "=r"(r) : "f"(x));
    return r;
}
__device__ __forceinline__ void mma_tf32(float* d, const uint32_t* a,
                                         const uint32_t* b) {
    asm volatile(
        "mma.sync.aligned.m16n8k8.row.col.f32.tf32.tf32.f32 "
        "{%0,%1,%2,%3}, {%4,%5,%6,%7}, {%8,%9}, {%0,%1,%2,%3};\n"
        : "+f"(d[0]), "+f"(d[1]), "+f"(d[2]), "+f"(d[3])
        : "r"(a[0]), "r"(a[1]), "r"(a[2]), "r"(a[3]), "r"(b[0]), "r"(b[1]));
}

// ============================================================================
// Tensor-core tf32 GEMM: 128x128x16 tiles, double-buffered, 256 threads.
//   C[m,n] = sum_k A[m,k] * W[n,k]   (W row-major N x K)
//   ATRANS:   A stored K x MTOT row-major (d-major activations)
//   SOFTPLUS: C = softplus(acc + bias[n])
// C written m-major (ldc). Requires K % 16 == 0, M == MTOT. N guarded.
// Warp grid 2x4 (warp tile 64x32); mma m16n8k8: 4 m-frags x 4 n-frags.
// smem [k][m] stride 136 -> bank = (8k + m) % 32, conflict-free frag loads.
// ============================================================================
constexpr int TBM = 128, TBN = 128, TBK = 16;
constexpr int TSAP = 136;

template<bool ATRANS, bool SOFTPLUS>
__global__ void __launch_bounds__(256, 2) tgemm_kernel(
    const float* __restrict__ A, int lda,
    const float* __restrict__ W,        // N x K
    const float* __restrict__ bias,
    float* __restrict__ C, int ldc,
    int N, int K)
{
    __shared__ uint32_t As[2][TBK][TSAP];
    __shared__ uint32_t Bs[2][TBK][TSAP];

    const int tid  = threadIdx.x;
    const int bm   = blockIdx.y * TBM;
    const int bn   = blockIdx.x * TBN;
    const int wid  = tid >> 5;
    const int lane = tid & 31;
    const int wm   = (wid & 1) * 64;     // warp m-offset in tile
    const int wn   = (wid >> 1) * 32;    // warp n-offset in tile
    const int gid  = lane >> 2;          // 0..7
    const int tig  = lane & 3;           // 0..3

    float acc[4][4][4];                  // [mi][ni][c0..c3]
    #pragma unroll
    for (int i = 0; i < 4; i++)
        #pragma unroll
        for (int j = 0; j < 4; j++)
            #pragma unroll
            for (int c = 0; c < 4; c++) acc[i][j][c] = 0.0f;

    float4 pa[2], pb[2];

    auto gloadA = [&](int k0) {
        #pragma unroll
        for (int it = 0; it < 2; it++) {
            int s = tid + it * 256;
            if (ATRANS) {
                int kk = s >> 5;                 // 0..15
                int mc = (s & 31) * 4;           // 0..124
                pa[it] = *reinterpret_cast<const float4*>(
                    A + (size_t)(k0 + kk) * MTOT + bm + mc);
            } else {
                int row = s >> 2;                // 0..127
                int kc  = (s & 3) * 4;
                pa[it] = *reinterpret_cast<const float4*>(
                    A + (size_t)(bm + row) * lda + k0 + kc);
            }
        }
    };
    auto gloadB = [&](int k0) {
        #pragma unroll
        for (int it = 0; it < 2; it++) {
            int s = tid + it * 256;
            int n  = s >> 2;
            int kc = (s & 3) * 4;
            if (bn + n < N)
                pb[it] = *reinterpret_cast<const float4*>(
                    W + (size_t)(bn + n) * K + k0 + kc);
            else
                pb[it] = make_float4(0.f, 0.f, 0.f, 0.f);
        }
    };
    auto sstore = [&](int st) {
        #pragma unroll
        for (int it = 0; it < 2; it++) {
            int s = tid + it * 256;
            if (ATRANS) {
                int kk = s >> 5;
                int mc = (s & 31) * 4;
                As[st][kk][mc + 0] = f2tf32(pa[it].x);
                As[st][kk][mc + 1] = f2tf32(pa[it].y);
                As[st][kk][mc + 2] = f2tf32(pa[it].z);
                As[st][kk][mc + 3] = f2tf32(pa[it].w);
            } else {
                int row = s >> 2;
                int kc  = (s & 3) * 4;
                As[st][kc + 0][row] = f2tf32(pa[it].x);
                As[st][kc + 1][row] = f2tf32(pa[it].y);
                As[st][kc + 2][row] = f2tf32(pa[it].z);
                As[st][kc + 3][row] = f2tf32(pa[it].w);
            }
            int n  = s >> 2;
            int kc = (s & 3) * 4;
            Bs[st][kc + 0][n] = f2tf32(pb[it].x);
            Bs[st][kc + 1][n] = f2tf32(pb[it].y);
            Bs[st][kc + 2][n] = f2tf32(pb[it].z);
            Bs[st][kc + 3][n] = f2tf32(pb[it].w);
        }
    };

    gloadA(0); gloadB(0);
    sstore(0);
    __syncthreads();

    const int kt = K / TBK;
    int st = 0;
    for (int it = 0; it < kt; it++) {
        const bool more = (it + 1) < kt;
        if (more) { gloadA((it + 1) * TBK); gloadB((it + 1) * TBK); }

        #pragma unroll
        for (int ks = 0; ks < 2; ks++) {
            const int kb = ks * 8;
            uint32_t afr[4][4], bfr[4][2];
            #pragma unroll
            for (int mi = 0; mi < 4; mi++) {
                int r = wm + mi * 16 + gid;
                afr[mi][0] = As[st][kb + tig][r];
                afr[mi][1] = As[st][kb + tig][r + 8];
                afr[mi][2] = As[st][kb + tig + 4][r];
                afr[mi][3] = As[st][kb + tig + 4][r + 8];
            }
            #pragma unroll
            for (int ni = 0; ni < 4; ni++) {
                int c = wn + ni * 8 + gid;
                bfr[ni][0] = Bs[st][kb + tig][c];
                bfr[ni][1] = Bs[st][kb + tig + 4][c];
            }
            #pragma unroll
            for (int mi = 0; mi < 4; mi++)
                #pragma unroll
                for (int ni = 0; ni < 4; ni++)
                    mma_tf32(acc[mi][ni], afr[mi], bfr[ni]);
        }
        if (more) {
            sstore(st ^ 1);
            __syncthreads();
        }
        st ^= 1;
    }

    // ---- epilogue: m-major C, N-guarded (N even, c even => c+1 < N) ----
    #pragma unroll
    for (int mi = 0; mi < 4; mi++) {
        int r = bm + wm + mi * 16 + gid;
        #pragma unroll
        for (int ni = 0; ni < 4; ni++) {
            int c = bn + wn + ni * 8 + tig * 2;
            if (c < N) {
                float d0 = acc[mi][ni][0], d1 = acc[mi][ni][1];
                float d2 = acc[mi][ni][2], d3 = acc[mi][ni][3];
                if (SOFTPLUS) {
                    float b0 = bias[c], b1 = bias[c + 1];
                    d0 = softplusf(d0 + b0); d1 = softplusf(d1 + b1);
                    d2 = softplusf(d2 + b0); d3 = softplusf(d3 + b1);
                }
                C[(size_t)r * ldc + c]           = d0;
                C[(size_t)r * ldc + c + 1]       = d1;
                C[(size_t)(r + 8) * ldc + c]     = d2;
                C[(size_t)(r + 8) * ldc + c + 1] = d3;
            }
        }
    }
}

// ----------------------------------------------------------------------------
// 32x32 tiled transpose: in (R x Ccols) -> out (Ccols x R). R,C % 32 == 0.
// ----------------------------------------------------------------------------
__global__ void transpose_kernel(const float* __restrict__ in,
                                 float* __restrict__ out, int R, int Ccols)
{
    __shared__ float tile[32][33];
    int c0 = blockIdx.x * 32, r0 = blockIdx.y * 32;
    int x = threadIdx.x, y = threadIdx.y;
    #pragma unroll
    for (int i = 0; i < 32; i += 8)
        tile[y + i][x] = in[(size_t)(r0 + y + i) * Ccols + c0 + x];
    __syncthreads();
    #pragma unroll
    for (int i = 0; i < 32; i += 8)
        out[(size_t)(c0 + y + i) * R + r0 + x] = tile[x][y + i];
}

// ----------------------------------------------------------------------------
// Causal depthwise conv (k=4) + SiLU on d-major xs (rows 0..DI-1 of xzT).
// ----------------------------------------------------------------------------
__global__ void conv_silu_kernel(const float* __restrict__ xzT,
                                 const float* __restrict__ cw,
                                 const float* __restrict__ cb,
                                 float* __restrict__ uT)
{
    int i = blockIdx.x * blockDim.x + threadIdx.x;   // DI*MTOT threads
    int d = i >> 13;             // / 8192
    int m = i & 8191;
    int t = m & 1023;
    const float* src = xzT + (size_t)d * MTOT + m;
    float w0 = cw[d * 4 + 0], w1 = cw[d * 4 + 1];
    float w2 = cw[d * 4 + 2], w3 = cw[d * 4 + 3];
    float acc = cb[d];
    if (t >= 3) acc = fmaf(src[-3], w0, acc);
    if (t >= 2) acc = fmaf(src[-2], w1, acc);
    if (t >= 1) acc = fmaf(src[-1], w2, acc);
    acc = fmaf(src[0], w3, acc);
    uT[(size_t)d * MTOT + m] = siluf(acc);
}

// ----------------------------------------------------------------------------
// Selective scan. One warp = 2 channels of one batch; lane l owns states
// (l, l+32). Fused skip + gate epilogue.
// ----------------------------------------------------------------------------
__global__ void __launch_bounds__(128) ssm_scan_kernel(
    const float* __restrict__ proj,    // (m, 176)
    const float* __restrict__ dtT,     // (d, m)
    const float* __restrict__ uT,      // (d, m)
    const float* __restrict__ xzT,     // (3072, m); z at rows 1536+d
    const float* __restrict__ A_log,   // (d, 64)
    const float* __restrict__ Dparam,  // (d)
    float* __restrict__ yT)            // (d, m)
{
    const unsigned FULL = 0xFFFFFFFFu;
    int w    = (blockIdx.x * blockDim.x + threadIdx.x) >> 5;  // 0..6143
    int lane = threadIdx.x & 31;
    int b  = w / (DI / 2);
    int d0 = (w % (DI / 2)) * 2;
    int d1 = d0 + 1;

    float A00 = -__expf(A_log[(size_t)d0 * NS + lane]);
    float A01 = -__expf(A_log[(size_t)d0 * NS + lane + 32]);
    float A10 = -__expf(A_log[(size_t)d1 * NS + lane]);
    float A11 = -__expf(A_log[(size_t)d1 * NS + lane + 32]);
    float D0 = Dparam[d0], D1 = Dparam[d1];

    float h00 = 0.f, h01 = 0.f, h10 = 0.f, h11 = 0.f;

    for (int tc = 0; tc < LL; tc += 32) {
        size_t mb = (size_t)b * LL + tc;
        float dtv0 = dtT[(size_t)d0 * MTOT + mb + lane];
        float dtv1 = dtT[(size_t)d1 * MTOT + mb + lane];
        float uv0  = uT [(size_t)d0 * MTOT + mb + lane];
        float uv1  = uT [(size_t)d1 * MTOT + mb + lane];
        float zv0  = xzT[(size_t)(DI + d0) * MTOT + mb + lane];
        float zv1  = xzT[(size_t)(DI + d1) * MTOT + mb + lane];

        float y0keep = 0.f, y1keep = 0.f;
        #pragma unroll 8
        for (int j = 0; j < 32; j++) {
            const float* pr = proj + (mb + j) * PROJC;
            float Bn0 = pr[48  + lane];
            float Bn1 = pr[80  + lane];
            float Cn0 = pr[112 + lane];
            float Cn1 = pr[144 + lane];
            float dt0 = __shfl_sync(FULL, dtv0, j);
            float dt1 = __shfl_sync(FULL, dtv1, j);
            float u0  = __shfl_sync(FULL, uv0, j);
            float u1  = __shfl_sync(FULL, uv1, j);
            float du0 = dt0 * u0;
            float du1 = dt1 * u1;
            h00 = fmaf(__expf(dt0 * A00), h00, du0 * Bn0);
            h01 = fmaf(__expf(dt0 * A01), h01, du0 * Bn1);
            h10 = fmaf(__expf(dt1 * A10), h10, du1 * Bn0);
            h11 = fmaf(__expf(dt1 * A11), h11, du1 * Bn1);
            float y0 = fmaf(h00, Cn0, h01 * Cn1);
            float y1 = fmaf(h10, Cn0, h11 * Cn1);
            #pragma unroll
            for (int off = 16; off; off >>= 1) {
                y0 += __shfl_xor_sync(FULL, y0, off);
                y1 += __shfl_xor_sync(FULL, y1, off);
            }
            if (lane == j) { y0keep = y0; y1keep = y1; }
        }
        float out0 = (y0keep + uv0 * D0) * siluf(zv0);
        float out1 = (y1keep + uv1 * D1) * siluf(zv1);
        yT[(size_t)d0 * MTOT + mb + lane] = out0;
        yT[(size_t)d1 * MTOT + mb + lane] = out1;
    }
}

// ----------------------------------------------------------------------------
// kernel_launch
// ----------------------------------------------------------------------------
extern "C" void kernel_launch(void* const* d_in, const int* in_sizes, int n_in,
                              void* d_out, int out_size)
{
    const float* x     = (const float*)d_in[0];
    const float* W_in  = (const float*)d_in[1];
    const float* cw    = (const float*)d_in[2];
    const float* cb    = (const float*)d_in[3];
    const float* W_x   = (const float*)d_in[4];
    const float* W_dt  = (const float*)d_in[5];
    const float* b_dt  = (const float*)d_in[6];
    const float* A_log = (const float*)d_in[7];
    const float* Dp    = (const float*)d_in[8];
    const float* W_out = (const float*)d_in[9];

    float *xz, *xzT, *uT, *proj, *dtT, *yT, *mid;
    cudaGetSymbolAddress((void**)&xz,   g_xz);
    cudaGetSymbolAddress((void**)&xzT,  g_xzT);
    cudaGetSymbolAddress((void**)&uT,   g_uT);
    cudaGetSymbolAddress((void**)&proj, g_proj);
    cudaGetSymbolAddress((void**)&dtT,  g_dtT);
    cudaGetSymbolAddress((void**)&yT,   g_yT);
    cudaGetSymbolAddress((void**)&mid,  g_mid);

    const dim3 tb256(256);
    const int MB = MTOT / TBM;   // 64

    for (int l = 0; l < 2; l++) {
        const float* xin = (l == 0) ? x : mid;
        float* xout = (l == 1) ? (float*)d_out : mid;

        // 1. in-proj: xz[m,3072] = xin @ W_in^T   (tf32 tensor cores)
        tgemm_kernel<false, false>
            <<<dim3(XZC / TBN, MB), tb256>>>(
                xin, DM, W_in + (size_t)l * XZC * DM, nullptr,
                xz, XZC, XZC, DM);

        // 2. transpose xz -> xzT (d-major xs and z)
        transpose_kernel<<<dim3(XZC / 32, MTOT / 32), dim3(32, 8)>>>(
            xz, xzT, MTOT, XZC);

        // 3. causal depthwise conv + silu -> uT (d-major)
        conv_silu_kernel<<<(DI * MTOT) / 256, tb256>>>(
            xzT, cw + (size_t)l * DI * 4, cb + (size_t)l * DI, uT);

        // 4. x-proj: proj[m,176] = u @ W_x^T  (tf32, N guarded)
        tgemm_kernel<true, false>
            <<<dim3((PROJC + TBN - 1) / TBN, MB), tb256>>>(
                uT, 0, W_x + (size_t)l * PROJC * DI, nullptr,
                proj, PROJC, PROJC, DI);

        // 5. dt (m-major, fused softplus) into xz scratch (tf32)
        tgemm_kernel<false, true>
            <<<dim3(DI / TBN, MB), tb256>>>(
                proj, PROJC, W_dt + (size_t)l * DI * DTR,
                b_dt + (size_t)l * DI, xz, DI, DI, DTR);

        // 6. transpose dt_m -> dtT (d-major)
        transpose_kernel<<<dim3(DI / 32, MTOT / 32), dim3(32, 8)>>>(
            xz, dtT, MTOT, DI);

        // 7. selective scan + skip + gate -> yT (d-major)
        ssm_scan_kernel<<<(BB * (DI / 2)) / 4, dim3(128)>>>(
            proj, dtT, uT, xzT,
            A_log + (size_t)l * DI * NS, Dp + (size_t)l * DI, yT);

        // 8. out-proj: xout[m,768] = y @ W_out^T  (tf32)
        tgemm_kernel<true, false>
            <<<dim3(DM / TBN, MB), tb256>>>(
                yT, 0, W_out + (size_t)l * DM * DI, nullptr,
                xout, DM, DM, DI);
    }
}

// round 7
// speedup vs baseline: 1.9036x; 1.1167x over previous
#include <cuda_runtime.h>
#include <cstdint>

// ----------------------------------------------------------------------------
// Problem constants (fixed shapes)
// ----------------------------------------------------------------------------
constexpr int BB   = 8;
constexpr int LL   = 1024;
constexpr int DM   = 768;
constexpr int DI   = 1536;
constexpr int NS   = 64;
constexpr int DTR  = 48;
constexpr int MTOT = BB * LL;        // 8192
constexpr int XZC  = 2 * DI;         // 3072
constexpr int PROJC = DTR + 2 * NS;  // 176

// ----------------------------------------------------------------------------
// Scratch (device globals; no allocation allowed)
// ----------------------------------------------------------------------------
__device__ float g_xz  [MTOT * XZC];   // in-proj out (m-major); reused for dt_m
__device__ float g_xzT [MTOT * XZC];   // (3072, m)
__device__ float g_uT  [MTOT * DI];    // (d, m) conv+silu, full precision
__device__ float g_uTr [MTOT * DI];    // (d, m) conv+silu, tf32-rounded
__device__ float g_proj[MTOT * PROJC]; // (m, 176) [dt_r(tf32) | B | C]
__device__ float g_dtT [MTOT * DI];    // (d, m) softplus dt, full
__device__ float g_yT  [MTOT * DI];    // (d, m) scan out, tf32-rounded
__device__ float g_mid [MTOT * DM];    // inter-layer act (tf32-rounded)
__device__ float g_xr  [MTOT * DM];    // layer-0 input, tf32-rounded

constexpr int WIN_SZ  = 2 * XZC * DM;
constexpr int WX_SZ   = 2 * PROJC * DI;
constexpr int WDT_SZ  = 2 * DI * DTR;
constexpr int WOUT_SZ = 2 * DM * DI;
__device__ float g_win [WIN_SZ];
__device__ float g_wx  [WX_SZ];
__device__ float g_wdt [WDT_SZ];
__device__ float g_wout[WOUT_SZ];

// ----------------------------------------------------------------------------
// Helpers
// ----------------------------------------------------------------------------
__device__ __forceinline__ float siluf(float x) {
    return x * (1.0f / (1.0f + __expf(-x)));
}
__device__ __forceinline__ float softplusf(float x) {
    return fmaxf(x, 0.0f) + log1pf(__expf(-fabsf(x)));
}
__device__ __forceinline__ float tf32r(float x) {
    uint32_t r;
    asm("cvt.rna.tf32.f32 %0, %1;" : "=r"(r) : "f"(x));
    return __uint_as_float(r);
}
__device__ __forceinline__ float ex2f(float x) {   // MUFU EX2 (fast exp2)
    float r;
    asm("ex2.approx.f32 %0, %1;" : "=f"(r) : "f"(x));
    return r;
}
__device__ __forceinline__ void mma_tf32(float* d, const uint32_t* a,
                                         const uint32_t* b) {
    asm volatile(
        "mma.sync.aligned.m16n8k8.row.col.f32.tf32.tf32.f32 "
        "{%0,%1,%2,%3}, {%4,%5,%6,%7}, {%8,%9}, {%0,%1,%2,%3};\n"
        : "+f"(d[0]), "+f"(d[1]), "+f"(d[2]), "+f"(d[3])
        : "r"(a[0]), "r"(a[1]), "r"(a[2]), "r"(a[3]), "r"(b[0]), "r"(b[1]));
}
__device__ __forceinline__ void cpa16(float* smem, const float* g) {
    uint32_t dst = (uint32_t)__cvta_generic_to_shared(smem);
    asm volatile("cp.async.ca.shared.global [%0], [%1], 16;\n"
                 :: "r"(dst), "l"(g));
}
__device__ __forceinline__ void cpa16z(float* smem, const float* g, int sz) {
    uint32_t dst = (uint32_t)__cvta_generic_to_shared(smem);
    asm volatile("cp.async.ca.shared.global [%0], [%1], 16, %2;\n"
                 :: "r"(dst), "l"(g), "r"(sz));
}

// ----------------------------------------------------------------------------
// tf32 rounding prep kernel (float4; n % 4 == 0)
// ----------------------------------------------------------------------------
__global__ void round_tf32_kernel(const float* __restrict__ in,
                                  float* __restrict__ out, int n)
{
    int i = (blockIdx.x * blockDim.x + threadIdx.x) * 4;
    if (i < n) {
        float4 v = *reinterpret_cast<const float4*>(in + i);
        v.x = tf32r(v.x); v.y = tf32r(v.y);
        v.z = tf32r(v.z); v.w = tf32r(v.w);
        *reinterpret_cast<float4*>(out + i) = v;
    }
}

// ============================================================================
// Tensor-core tf32 GEMM, cp.async 2-stage pipeline. Inputs PRE-ROUNDED tf32.
//   C[m,n] = sum_k A[m,k] * W[n,k]  (W row-major N x K)
//   ATRANS: A stored K x MTOT (d-major);  else A m-major with lda.
//   MODE: 0 none | 1 softplus(+bias) | 2 round-all | 3 round cols < DTR
// Block 128x128x16, 256 thr, warp grid 2x4 (warp tile 64x32), mma m16n8k8.
// smem: ATRANS A -> [k][m] stride 136 ; else A -> [m][k] stride 20;
//       B always [n][k] stride 20. All fragment reads bank-conflict-free.
// ============================================================================
constexpr int TBM = 128, TBN = 128, TBK = 16;
constexpr int SKM = 136;      // [k][m] stride
constexpr int SMK = 20;       // [m][k]/[n][k] stride
constexpr int ASTG = 2560;    // max(16*136, 128*20)
constexpr int BSTG = 2560;

template<bool ATRANS, int MODE>
__global__ void __launch_bounds__(256, 2) tgemm_kernel(
    const float* __restrict__ A, int lda,
    const float* __restrict__ W,
    const float* __restrict__ bias,
    float* __restrict__ C, int ldc,
    int N, int K)
{
    __shared__ float As[2][ASTG];
    __shared__ float Bs[2][BSTG];

    const int tid  = threadIdx.x;
    const int bm   = blockIdx.y * TBM;
    const int bn   = blockIdx.x * TBN;
    const int wid  = tid >> 5;
    const int lane = tid & 31;
    const int wm   = (wid & 1) * 64;
    const int wn   = (wid >> 1) * 32;
    const int gid  = lane >> 2;
    const int tig  = lane & 3;

    float acc[4][4][4];
    #pragma unroll
    for (int i = 0; i < 4; i++)
        #pragma unroll
        for (int j = 0; j < 4; j++)
            #pragma unroll
            for (int c = 0; c < 4; c++) acc[i][j][c] = 0.0f;

    auto issue_load = [&](int k0, int st) {
        #pragma unroll
        for (int itr = 0; itr < 2; itr++) {
            int s = tid + itr * 256;
            if (ATRANS) {
                int kk = s >> 5, mc = (s & 31) * 4;
                cpa16(&As[st][kk * SKM + mc],
                      A + (size_t)(k0 + kk) * MTOT + bm + mc);
            } else {
                int row = s >> 2, kc = (s & 3) * 4;
                cpa16(&As[st][row * SMK + kc],
                      A + (size_t)(bm + row) * lda + k0 + kc);
            }
            int n = s >> 2, kc = (s & 3) * 4;
            cpa16z(&Bs[st][n * SMK + kc],
                   W + (size_t)(bn + n) * K + k0 + kc,
                   (bn + n < N) ? 16 : 0);
        }
        asm volatile("cp.async.commit_group;\n");
    };

    issue_load(0, 0);

    const int kt = K / TBK;
    int st = 0;
    for (int it = 0; it < kt; it++) {
        asm volatile("cp.async.wait_group 0;\n");
        __syncthreads();
        if (it + 1 < kt) issue_load((it + 1) * TBK, st ^ 1);

        #pragma unroll
        for (int ks = 0; ks < 2; ks++) {
            const int kb = ks * 8;
            uint32_t afr[4][4], bfr[4][2];
            #pragma unroll
            for (int mi = 0; mi < 4; mi++) {
                int r = wm + mi * 16 + gid;
                if (ATRANS) {
                    afr[mi][0] = __float_as_uint(As[st][(kb + tig) * SKM + r]);
                    afr[mi][1] = __float_as_uint(As[st][(kb + tig) * SKM + r + 8]);
                    afr[mi][2] = __float_as_uint(As[st][(kb + tig + 4) * SKM + r]);
                    afr[mi][3] = __float_as_uint(As[st][(kb + tig + 4) * SKM + r + 8]);
                } else {
                    afr[mi][0] = __float_as_uint(As[st][r * SMK + kb + tig]);
                    afr[mi][1] = __float_as_uint(As[st][(r + 8) * SMK + kb + tig]);
                    afr[mi][2] = __float_as_uint(As[st][r * SMK + kb + tig + 4]);
                    afr[mi][3] = __float_as_uint(As[st][(r + 8) * SMK + kb + tig + 4]);
                }
            }
            #pragma unroll
            for (int ni = 0; ni < 4; ni++) {
                int c = wn + ni * 8 + gid;
                bfr[ni][0] = __float_as_uint(Bs[st][c * SMK + kb + tig]);
                bfr[ni][1] = __float_as_uint(Bs[st][c * SMK + kb + tig + 4]);
            }
            #pragma unroll
            for (int mi = 0; mi < 4; mi++)
                #pragma unroll
                for (int ni = 0; ni < 4; ni++)
                    mma_tf32(acc[mi][ni], afr[mi], bfr[ni]);
        }
        st ^= 1;
    }

    // ---- epilogue (m-major C; N even, c even => c+1 < N) ----
    #pragma unroll
    for (int mi = 0; mi < 4; mi++) {
        int r = bm + wm + mi * 16 + gid;
        #pragma unroll
        for (int ni = 0; ni < 4; ni++) {
            int c = bn + wn + ni * 8 + tig * 2;
            if (c < N) {
                float d0 = acc[mi][ni][0], d1 = acc[mi][ni][1];
                float d2 = acc[mi][ni][2], d3 = acc[mi][ni][3];
                if (MODE == 1) {
                    float b0 = bias[c], b1 = bias[c + 1];
                    d0 = softplusf(d0 + b0); d1 = softplusf(d1 + b1);
                    d2 = softplusf(d2 + b0); d3 = softplusf(d3 + b1);
                }
                if (MODE == 2) {
                    d0 = tf32r(d0); d1 = tf32r(d1);
                    d2 = tf32r(d2); d3 = tf32r(d3);
                }
                if (MODE == 3 && c < DTR) {   // c,c+1 both < 48 (c even)
                    d0 = tf32r(d0); d1 = tf32r(d1);
                    d2 = tf32r(d2); d3 = tf32r(d3);
                }
                C[(size_t)r * ldc + c]           = d0;
                C[(size_t)r * ldc + c + 1]       = d1;
                C[(size_t)(r + 8) * ldc + c]     = d2;
                C[(size_t)(r + 8) * ldc + c + 1] = d3;
            }
        }
    }
}

// ----------------------------------------------------------------------------
// 32x32 tiled transpose: in (R x Ccols) -> out (Ccols x R). R,C % 32 == 0.
// ----------------------------------------------------------------------------
__global__ void transpose_kernel(const float* __restrict__ in,
                                 float* __restrict__ out, int R, int Ccols)
{
    __shared__ float tile[32][33];
    int c0 = blockIdx.x * 32, r0 = blockIdx.y * 32;
    int x = threadIdx.x, y = threadIdx.y;
    #pragma unroll
    for (int i = 0; i < 32; i += 8)
        tile[y + i][x] = in[(size_t)(r0 + y + i) * Ccols + c0 + x];
    __syncthreads();
    #pragma unroll
    for (int i = 0; i < 32; i += 8)
        out[(size_t)(c0 + y + i) * R + r0 + x] = tile[x][y + i];
}

// ----------------------------------------------------------------------------
// Causal depthwise conv (k=4) + SiLU. Writes full (uT) + tf32-rounded (uTr).
// ----------------------------------------------------------------------------
__global__ void conv_silu_kernel(const float* __restrict__ xzT,
                                 const float* __restrict__ cw,
                                 const float* __restrict__ cb,
                                 float* __restrict__ uT,
                                 float* __restrict__ uTr)
{
    int i = blockIdx.x * blockDim.x + threadIdx.x;
    int d = i >> 13;
    int m = i & 8191;
    int t = m & 1023;
    const float* src = xzT + (size_t)d * MTOT + m;
    float w0 = cw[d * 4 + 0], w1 = cw[d * 4 + 1];
    float w2 = cw[d * 4 + 2], w3 = cw[d * 4 + 3];
    float acc = cb[d];
    if (t >= 3) acc = fmaf(src[-3], w0, acc);
    if (t >= 2) acc = fmaf(src[-2], w1, acc);
    if (t >= 1) acc = fmaf(src[-1], w2, acc);
    acc = fmaf(src[0], w3, acc);
    float s = siluf(acc);
    uT [(size_t)d * MTOT + m] = s;
    uTr[(size_t)d * MTOT + m] = tf32r(s);
}

// ----------------------------------------------------------------------------
// Selective scan. One warp = 2 channels of one batch; lane l owns states
// (l, l+32). Fused skip + gate. Stores tf32-rounded yT (out-proj A input).
// ----------------------------------------------------------------------------
__global__ void __launch_bounds__(128) ssm_scan_kernel(
    const float* __restrict__ proj,
    const float* __restrict__ dtT,
    const float* __restrict__ uT,
    const float* __restrict__ xzT,
    const float* __restrict__ A_log,
    const float* __restrict__ Dparam,
    float* __restrict__ yT)
{
    const unsigned FULL = 0xFFFFFFFFu;
    const float L2E = 1.4426950408889634f;
    int w    = (blockIdx.x * blockDim.x + threadIdx.x) >> 5;
    int lane = threadIdx.x & 31;
    int b  = w / (DI / 2);
    int d0 = (w % (DI / 2)) * 2;
    int d1 = d0 + 1;

    // A scaled by log2(e): exp(dt*A) == ex2f(dt*A2)
    float A00 = -__expf(A_log[(size_t)d0 * NS + lane])      * L2E;
    float A01 = -__expf(A_log[(size_t)d0 * NS + lane + 32]) * L2E;
    float A10 = -__expf(A_log[(size_t)d1 * NS + lane])      * L2E;
    float A11 = -__expf(A_log[(size_t)d1 * NS + lane + 32]) * L2E;
    float D0 = Dparam[d0], D1 = Dparam[d1];

    float h00 = 0.f, h01 = 0.f, h10 = 0.f, h11 = 0.f;

    for (int tc = 0; tc < LL; tc += 32) {
        size_t mb = (size_t)b * LL + tc;
        float dtv0 = dtT[(size_t)d0 * MTOT + mb + lane];
        float dtv1 = dtT[(size_t)d1 * MTOT + mb + lane];
        float uv0  = uT [(size_t)d0 * MTOT + mb + lane];
        float uv1  = uT [(size_t)d1 * MTOT + mb + lane];
        float zv0  = xzT[(size_t)(DI + d0) * MTOT + mb + lane];
        float zv1  = xzT[(size_t)(DI + d1) * MTOT + mb + lane];

        float y0keep = 0.f, y1keep = 0.f;
        #pragma unroll 8
        for (int j = 0; j < 32; j++) {
            const float* pr = proj + (mb + j) * PROJC;
            float Bn0 = pr[48  + lane];
            float Bn1 = pr[80  + lane];
            float Cn0 = pr[112 + lane];
            float Cn1 = pr[144 + lane];
            float dt0 = __shfl_sync(FULL, dtv0, j);
            float dt1 = __shfl_sync(FULL, dtv1, j);
            float u0  = __shfl_sync(FULL, uv0, j);
            float u1  = __shfl_sync(FULL, uv1, j);
            float du0 = dt0 * u0;
            float du1 = dt1 * u1;
            h00 = fmaf(ex2f(dt0 * A00), h00, du0 * Bn0);
            h01 = fmaf(ex2f(dt0 * A01), h01, du0 * Bn1);
            h10 = fmaf(ex2f(dt1 * A10), h10, du1 * Bn0);
            h11 = fmaf(ex2f(dt1 * A11), h11, du1 * Bn1);
            float y0 = fmaf(h00, Cn0, h01 * Cn1);
            float y1 = fmaf(h10, Cn0, h11 * Cn1);
            #pragma unroll
            for (int off = 16; off; off >>= 1) {
                y0 += __shfl_xor_sync(FULL, y0, off);
                y1 += __shfl_xor_sync(FULL, y1, off);
            }
            if (lane == j) { y0keep = y0; y1keep = y1; }
        }
        float out0 = (y0keep + uv0 * D0) * siluf(zv0);
        float out1 = (y1keep + uv1 * D1) * siluf(zv1);
        yT[(size_t)d0 * MTOT + mb + lane] = tf32r(out0);
        yT[(size_t)d1 * MTOT + mb + lane] = tf32r(out1);
    }
}

// ----------------------------------------------------------------------------
// kernel_launch
// ----------------------------------------------------------------------------
extern "C" void kernel_launch(void* const* d_in, const int* in_sizes, int n_in,
                              void* d_out, int out_size)
{
    const float* x     = (const float*)d_in[0];
    const float* W_in  = (const float*)d_in[1];
    const float* cw    = (const float*)d_in[2];
    const float* cb    = (const float*)d_in[3];
    const float* W_x   = (const float*)d_in[4];
    const float* W_dt  = (const float*)d_in[5];
    const float* b_dt  = (const float*)d_in[6];
    const float* A_log = (const float*)d_in[7];
    const float* Dp    = (const float*)d_in[8];
    const float* W_out = (const float*)d_in[9];

    float *xz, *xzT, *uT, *uTr, *proj, *dtT, *yT, *mid, *xr;
    float *win, *wx, *wdt, *wout;
    cudaGetSymbolAddress((void**)&xz,   g_xz);
    cudaGetSymbolAddress((void**)&xzT,  g_xzT);
    cudaGetSymbolAddress((void**)&uT,   g_uT);
    cudaGetSymbolAddress((void**)&uTr,  g_uTr);
    cudaGetSymbolAddress((void**)&proj, g_proj);
    cudaGetSymbolAddress((void**)&dtT,  g_dtT);
    cudaGetSymbolAddress((void**)&yT,   g_yT);
    cudaGetSymbolAddress((void**)&mid,  g_mid);
    cudaGetSymbolAddress((void**)&xr,   g_xr);
    cudaGetSymbolAddress((void**)&win,  g_win);
    cudaGetSymbolAddress((void**)&wx,   g_wx);
    cudaGetSymbolAddress((void**)&wdt,  g_wdt);
    cudaGetSymbolAddress((void**)&wout, g_wout);

    const dim3 tb256(256);
    const int MB = MTOT / TBM;   // 64

    // ---- tf32 pre-rounding (weights + layer-0 input) ----
    auto rgrid = [](int n) { return (n / 4 + 255) / 256; };
    round_tf32_kernel<<<rgrid(MTOT * DM), tb256>>>(x,     xr,   MTOT * DM);
    round_tf32_kernel<<<rgrid(WIN_SZ),    tb256>>>(W_in,  win,  WIN_SZ);
    round_tf32_kernel<<<rgrid(WX_SZ),     tb256>>>(W_x,   wx,   WX_SZ);
    round_tf32_kernel<<<rgrid(WDT_SZ),    tb256>>>(W_dt,  wdt,  WDT_SZ);
    round_tf32_kernel<<<rgrid(WOUT_SZ),   tb256>>>(W_out, wout, WOUT_SZ);

    for (int l = 0; l < 2; l++) {
        const float* xin = (l == 0) ? xr : mid;   // both tf32-rounded
        float* xout = (l == 1) ? (float*)d_out : mid;

        // 1. in-proj: xz[m,3072] = xin @ W_in^T
        tgemm_kernel<false, 0>
            <<<dim3(XZC / TBN, MB), tb256>>>(
                xin, DM, win + (size_t)l * XZC * DM, nullptr,
                xz, XZC, XZC, DM);

        // 2. transpose xz -> xzT (d-major xs and z; full precision)
        transpose_kernel<<<dim3(XZC / 32, MTOT / 32), dim3(32, 8)>>>(
            xz, xzT, MTOT, XZC);

        // 3. conv + silu -> uT (full) + uTr (rounded)
        conv_silu_kernel<<<(DI * MTOT) / 256, tb256>>>(
            xzT, cw + (size_t)l * DI * 4, cb + (size_t)l * DI, uT, uTr);

        // 4. x-proj: proj[m,176] = u @ W_x^T ; rounds dt_r cols (<48) only
        tgemm_kernel<true, 3>
            <<<dim3((PROJC + TBN - 1) / TBN, MB), tb256>>>(
                uTr, 0, wx + (size_t)l * PROJC * DI, nullptr,
                proj, PROJC, PROJC, DI);

        // 5. dt (m-major, fused softplus) into xz scratch
        tgemm_kernel<false, 1>
            <<<dim3(DI / TBN, MB), tb256>>>(
                proj, PROJC, wdt + (size_t)l * DI * DTR,
                b_dt + (size_t)l * DI, xz, DI, DI, DTR);

        // 6. transpose dt_m -> dtT (d-major, full precision)
        transpose_kernel<<<dim3(DI / 32, MTOT / 32), dim3(32, 8)>>>(
            xz, dtT, MTOT, DI);

        // 7. selective scan + skip + gate -> yT (rounded for out-proj)
        ssm_scan_kernel<<<(BB * (DI / 2)) / 4, dim3(128)>>>(
            proj, dtT, uT, xzT,
            A_log + (size_t)l * DI * NS, Dp + (size_t)l * DI, yT);

        // 8. out-proj: xout = y @ W_out^T ; l=0 rounds (feeds next in-proj)
        if (l == 0)
            tgemm_kernel<true, 2>
                <<<dim3(DM / TBN, MB), tb256>>>(
                    yT, 0, wout + (size_t)l * DM * DI, nullptr,
                    xout, DM, DM, DI);
        else
            tgemm_kernel<true, 0>
                <<<dim3(DM / TBN, MB), tb256>>>(
                    yT, 0, wout + (size_t)l * DM * DI, nullptr,
                    xout, DM, DM, DI);
    }
}